// round 7
// baseline (speedup 1.0000x reference)
#include <cuda_runtime.h>
#include <cuda_bf16.h>
#include <cstdint>
#include <math.h>

// Problem constants (B=8, H=W=128, C=384, window=8)
#define TOKENS   131072              // 8*128*128
#define CDIM     384
#define NQKV     1152
#define NWIN     2048                // 8 * 16 * 16 windows

// ---------------------------------------------------------------------------
// Scratch (allocation-free rule: __device__ globals)
// ---------------------------------------------------------------------------
__device__ float          g_qkv[(size_t)TOKENS * NQKV];    // fp32 qkv (604 MB)
__device__ __nv_bfloat16  g_A2 [(size_t)TOKENS * 768];     // A split planes [hi384|lo384]
__device__ __nv_bfloat16  g_Whi1[(size_t)NQKV * CDIM];     // w_qkv^T hi  [N][K]
__device__ __nv_bfloat16  g_Wlo1[(size_t)NQKV * CDIM];     // w_qkv^T lo
__device__ __nv_bfloat16  g_Whi3[(size_t)CDIM * CDIM];     // w_proj^T hi
__device__ __nv_bfloat16  g_Wlo3[(size_t)CDIM * CDIM];     // w_proj^T lo

__device__ __forceinline__ uint32_t smem_u32(const void* p) {
    uint32_t a;
    asm("{ .reg .u64 tmp; cvta.to.shared.u64 tmp, %1; cvt.u32.u64 %0, tmp; }"
        : "=r"(a) : "l"(p));
    return a;
}

// Split a float2 into packed bf16x2 hi and lo (residual) parts.
__device__ __forceinline__ void split2(float x, float y, uint32_t& hi, uint32_t& lo) {
    uint32_t h;
    asm("cvt.rn.bf16x2.f32 %0, %1, %2;" : "=r"(h) : "f"(y), "f"(x));
    float h0 = __uint_as_float(h << 16);
    float h1 = __uint_as_float(h & 0xffff0000u);
    float r0 = x - h0, r1 = y - h1;
    asm("cvt.rn.bf16x2.f32 %0, %1, %2;" : "=r"(lo) : "f"(r1), "f"(r0));
    hi = h;
}

__device__ __forceinline__ void mma16816(float* c, const uint32_t* a,
                                         uint32_t b0, uint32_t b1) {
    asm volatile(
        "mma.sync.aligned.m16n8k16.row.col.f32.bf16.bf16.f32 "
        "{%0,%1,%2,%3}, {%4,%5,%6,%7}, {%8,%9}, {%0,%1,%2,%3};\n"
        : "+f"(c[0]), "+f"(c[1]), "+f"(c[2]), "+f"(c[3])
        : "r"(a[0]), "r"(a[1]), "r"(a[2]), "r"(a[3]), "r"(b0), "r"(b1));
}

#define LDSM_X4(r, a) \
    asm volatile("ldmatrix.sync.aligned.m8n8.x4.shared.b16 {%0,%1,%2,%3}, [%4];" \
        : "=r"((r)[0]), "=r"((r)[1]), "=r"((r)[2]), "=r"((r)[3]) : "r"(a))

// ---------------------------------------------------------------------------
// Weight split + transpose: w [384 x N] fp32 -> Whi/Wlo [N x 384] bf16
// ---------------------------------------------------------------------------
__global__ __launch_bounds__(256) void split_w_kernel(
    const float* __restrict__ w, __nv_bfloat16* __restrict__ Whi,
    __nv_bfloat16* __restrict__ Wlo, int N)
{
    const int t = blockIdx.x * 256 + threadIdx.x;
    if (t >= N * CDIM) return;
    const int n = t / CDIM;
    const int k = t % CDIM;
    const float v = w[(size_t)k * N + n];
    __nv_bfloat16 h = __float2bfloat16(v);
    __nv_bfloat16 l = __float2bfloat16(v - __bfloat162float(h));
    Whi[(size_t)n * CDIM + k] = h;
    Wlo[(size_t)n * CDIM + k] = l;
}

// ---------------------------------------------------------------------------
// Split x rows: fp32 [TOKENS][384] -> g_A2 [TOKENS][hi 384 | lo 384] bf16
// ---------------------------------------------------------------------------
__global__ __launch_bounds__(256) void split_x_kernel(
    const float* __restrict__ in, __nv_bfloat16* __restrict__ out)
{
    const int t = blockIdx.x * 256 + threadIdx.x;    // t < TOKENS*96
    const int r = t / 96;
    const int c = (t % 96) * 4;
    float4 v = *(const float4*)(in + (size_t)r * CDIM + c);
    uint32_t h0, l0, h1, l1;
    split2(v.x, v.y, h0, l0);
    split2(v.z, v.w, h1, l1);
    __nv_bfloat16* o = out + (size_t)r * 768;
    *(uint32_t*)(o + c) = h0;
    *(uint32_t*)(o + c + 2) = h1;
    *(uint32_t*)(o + 384 + c) = l0;
    *(uint32_t*)(o + 384 + c + 2) = l1;
}

// ---------------------------------------------------------------------------
// HMMA GEMM v6: 64x64 warp tile (smem-traffic bound fix).
//   BM=256, BN=128, BK=32, 256 threads (8 warps: 4M x 2N), 1 CTA/SM, 255 regs.
//   Stage = A(2 planes x 256 x 64B) + B(2 planes x 128 x 64B) = 49152 B; x3.
//   Swizzle: 16B chunk ch at row r stored at ch ^ ((r>>1)&3).
// ---------------------------------------------------------------------------
#define STAGE_BYTES 49152u
__global__ __launch_bounds__(256, 1) void gemm_mma(
    const __nv_bfloat16* __restrict__ A2,
    const __nv_bfloat16* __restrict__ Bhi,
    const __nv_bfloat16* __restrict__ Blo,
    const float* __restrict__ bias,
    float* __restrict__ C, int Ndim)
{
    extern __shared__ __align__(16) char smem[];
    const uint32_t smemBase = smem_u32(smem);

    const int tid  = threadIdx.x;
    const int wid  = tid >> 5;
    const int lane = tid & 31;
    const int g    = lane >> 2;
    const int t4   = lane & 3;
    const int m0   = blockIdx.y * 256;
    const int n0   = blockIdx.x * 128;
    const int wm   = (wid & 3) * 64;   // warp M offset (4 warps x 64)
    const int wn   = (wid >> 2) * 64;  // warp N offset (2 warps x 64)

    // Per-thread cp.async descriptors: 12 chunks of 16B per stage
    // A chunks: 2048 (2 planes x 256 rows x 4), B chunks: 1024 (2 x 128 x 4)
    const __nv_bfloat16* srcs[12];
    uint32_t dsts[12];
#pragma unroll
    for (int i = 0; i < 12; i++) {
        const int id = tid + i * 256;          // < 3072
        if (id < 2048) {                       // A
            const int p  = id >> 10;
            const int r  = (id >> 2) & 255;
            const int ch = id & 3;
            srcs[i] = A2 + (size_t)(m0 + r) * 768 + p * 384 + ch * 8;
            const int chs = ch ^ ((r >> 1) & 3);
            dsts[i] = smemBase + (uint32_t)(p * 16384 + r * 64 + chs * 16);
        } else {                               // B
            const int id2 = id - 2048;
            const int p  = id2 >> 9;
            const int r  = (id2 >> 2) & 127;
            const int ch = id2 & 3;
            srcs[i] = (p ? Blo : Bhi) + (size_t)(n0 + r) * 384 + ch * 8;
            const int chs = ch ^ ((r >> 1) & 3);
            dsts[i] = smemBase + (uint32_t)(32768 + p * 8192 + r * 64 + chs * 16);
        }
    }

#define PREFETCH(s, off) do {                                                 \
        _Pragma("unroll")                                                     \
        for (int _i = 0; _i < 12; _i++) {                                     \
            asm volatile("cp.async.cg.shared.global [%0], [%1], 16;"          \
                :: "r"(dsts[_i] + (off)), "l"(srcs[_i] + (s) * 32));          \
        }                                                                     \
        asm volatile("cp.async.commit_group;" ::: "memory");                  \
    } while (0)

    // ldmatrix addressing
    const int la = lane & 15;
    const int hi = lane >> 4;
    const int sw = (la >> 1) & 3;
    const uint32_t cb0 = (uint32_t)(((0 | hi) ^ sw) * 16);
    const uint32_t cb1 = (uint32_t)(((2 | hi) ^ sw) * 16);
    // A hi plane @0 (lo +16384), B hi plane @32768 (lo +8192)
    const uint32_t aA[2] = { smemBase + (uint32_t)((wm + la) * 64) + cb0,
                             smemBase + (uint32_t)((wm + la) * 64) + cb1 };
    const uint32_t bA[2] = { smemBase + 32768 + (uint32_t)((wn + la) * 64) + cb0,
                             smemBase + 32768 + (uint32_t)((wn + la) * 64) + cb1 };

    float acc[4][8][4];
#pragma unroll
    for (int mt = 0; mt < 4; mt++)
#pragma unroll
        for (int nt = 0; nt < 8; nt++)
#pragma unroll
            for (int i = 0; i < 4; i++) acc[mt][nt][i] = 0.f;

    PREFETCH(0, 0);
    PREFETCH(1, STAGE_BYTES);

#pragma unroll
    for (int s = 0; s < 12; s++) {
        asm volatile("cp.async.wait_group 1;" ::: "memory");
        __syncthreads();
        if (s < 10) PREFETCH(s + 2, ((s + 2) % 3) * STAGE_BYTES);
        else asm volatile("cp.async.commit_group;" ::: "memory");
        const uint32_t off = (s % 3) * STAGE_BYTES;

#pragma unroll
        for (int kt = 0; kt < 2; kt++) {
            uint32_t ah[4][4], al[4][4];
#pragma unroll
            for (int mt = 0; mt < 4; mt++) {
                LDSM_X4(ah[mt], aA[kt] + off + mt * 1024);
                LDSM_X4(al[mt], aA[kt] + off + 16384 + mt * 1024);
            }
#pragma unroll
            for (int ntp = 0; ntp < 4; ntp++) {
                uint32_t bh[4], bl[4];
                LDSM_X4(bh, bA[kt] + off + ntp * 1024);
                LDSM_X4(bl, bA[kt] + off + 8192 + ntp * 1024);
                // pass hi*hi : 8 independent accumulators
#pragma unroll
                for (int mt = 0; mt < 4; mt++) {
                    mma16816(acc[mt][ntp * 2],     ah[mt], bh[0], bh[2]);
                    mma16816(acc[mt][ntp * 2 + 1], ah[mt], bh[1], bh[3]);
                }
                // pass lo*hi
#pragma unroll
                for (int mt = 0; mt < 4; mt++) {
                    mma16816(acc[mt][ntp * 2],     al[mt], bh[0], bh[2]);
                    mma16816(acc[mt][ntp * 2 + 1], al[mt], bh[1], bh[3]);
                }
                // pass hi*lo
#pragma unroll
                for (int mt = 0; mt < 4; mt++) {
                    mma16816(acc[mt][ntp * 2],     ah[mt], bl[0], bl[2]);
                    mma16816(acc[mt][ntp * 2 + 1], ah[mt], bl[1], bl[3]);
                }
            }
        }
    }
#undef PREFETCH

    // Epilogue: bias + store
#pragma unroll
    for (int mt = 0; mt < 4; mt++) {
        const int r0 = m0 + wm + mt * 16 + g;
#pragma unroll
        for (int nt = 0; nt < 8; nt++) {
            const int col = n0 + wn + (nt >> 1) * 16 + (nt & 1) * 8 + t4 * 2;
            float2 bv = *(const float2*)(bias + col);
            float2 v0 = make_float2(acc[mt][nt][0] + bv.x, acc[mt][nt][1] + bv.y);
            float2 v1 = make_float2(acc[mt][nt][2] + bv.x, acc[mt][nt][3] + bv.y);
            *(float2*)(C + (size_t)r0 * Ndim + col) = v0;
            *(float2*)(C + (size_t)(r0 + 8) * Ndim + col) = v1;
        }
    }
}

// ---------------------------------------------------------------------------
// Per-window attention (fp32 math; coalesced loads; swizzled transposed smem;
// epilogue writes split-bf16 planes to g_A2)
// ---------------------------------------------------------------------------
__global__ __launch_bounds__(256) void window_attn()
{
    const int gb  = blockIdx.x;
    const int b   = gb >> 8;
    const int win = gb & 255;
    const int wy  = win >> 4;
    const int wx  = win & 15;

    __shared__ int tok[64];
    __shared__ float Ss[64][65];
    __shared__ __align__(16) char raw[64 * 68 * 4];
    float (*Qs)[64] = (float(*)[64])raw;               // [32][64] swizzled cols
    float (*Ks)[64] = (float(*)[64])(raw + 8192);
    float (*Vs)[68] = (float(*)[68])raw;               // [64][68] overlay

    const int tid = threadIdx.x;
    if (tid < 64) {
        int py = tid >> 3, px = tid & 7;
        tok[tid] = b * 16384 + (wy * 8 + py) * 128 + (wx * 8 + px);
    }
    __syncthreads();

    const int tx  = tid & 15;
    const int ty  = tid >> 4;
    const int grp = tid >> 2;          // token index 0..63
    const int l   = tid & 3;           // lane-in-group

    const float* qb = g_qkv + (size_t)tok[grp] * NQKV;

    // ---- Phase 1: S = Q K^T ----
    float acc[4][4];
#pragma unroll
    for (int i = 0; i < 4; i++)
#pragma unroll
        for (int j = 0; j < 4; j++) acc[i][j] = 0.f;

    const int colq = grp ^ (l << 3);   // swizzled column (= grp ^ (kk&24))
    for (int kt = 0; kt < CDIM; kt += 32) {
        const float* qp = qb + kt + l * 8;
        float4 q0 = *(const float4*)qp;
        float4 q1 = *(const float4*)(qp + 4);
        float4 k0 = *(const float4*)(qp + CDIM);
        float4 k1 = *(const float4*)(qp + CDIM + 4);
        const int kk = l * 8;
        Qs[kk + 0][colq] = q0.x; Qs[kk + 1][colq] = q0.y;
        Qs[kk + 2][colq] = q0.z; Qs[kk + 3][colq] = q0.w;
        Qs[kk + 4][colq] = q1.x; Qs[kk + 5][colq] = q1.y;
        Qs[kk + 6][colq] = q1.z; Qs[kk + 7][colq] = q1.w;
        Ks[kk + 0][colq] = k0.x; Ks[kk + 1][colq] = k0.y;
        Ks[kk + 2][colq] = k0.z; Ks[kk + 3][colq] = k0.w;
        Ks[kk + 4][colq] = k1.x; Ks[kk + 5][colq] = k1.y;
        Ks[kk + 6][colq] = k1.z; Ks[kk + 7][colq] = k1.w;
        __syncthreads();
#pragma unroll
        for (int k = 0; k < 32; k++) {
            const int xv = k & 24;
            float4 a  = *(const float4*)&Qs[k][(ty * 4) ^ xv];
            float4 bb = *(const float4*)&Ks[k][(tx * 4) ^ xv];
            float av[4] = {a.x, a.y, a.z, a.w};
            float bv[4] = {bb.x, bb.y, bb.z, bb.w};
#pragma unroll
            for (int i = 0; i < 4; i++)
#pragma unroll
                for (int j = 0; j < 4; j++) acc[i][j] += av[i] * bv[j];
        }
        __syncthreads();
    }
#pragma unroll
    for (int i = 0; i < 4; i++)
#pragma unroll
        for (int j = 0; j < 4; j++) Ss[ty * 4 + i][tx * 4 + j] = acc[i][j];
    __syncthreads();

    // ---- Phase 2: softmax rows ----
    if (tid < 64) {
        float m = -1e30f;
#pragma unroll 8
        for (int j = 0; j < 64; j++) m = fmaxf(m, Ss[tid][j]);
        float s = 0.f;
#pragma unroll 8
        for (int j = 0; j < 64; j++) {
            float e = expf(Ss[tid][j] - m);
            Ss[tid][j] = e;
            s += e;
        }
        float inv = 1.f / s;
#pragma unroll 8
        for (int j = 0; j < 64; j++) Ss[tid][j] *= inv;
    }
    __syncthreads();

    // ---- Phase 3: O = P V ----
    for (int ct = 0; ct < CDIM; ct += 64) {
        const float* vp = qb + 2 * CDIM + ct;
#pragma unroll
        for (int u = 0; u < 4; u++) {
            float4 v = *(const float4*)(vp + u * 16 + l * 4);
            *(float4*)&Vs[grp][u * 16 + l * 4] = v;
        }
        __syncthreads();

        float o[4][4];
#pragma unroll
        for (int i = 0; i < 4; i++)
#pragma unroll
            for (int j = 0; j < 4; j++) o[i][j] = 0.f;
#pragma unroll
        for (int k = 0; k < 64; k++) {
            float a0 = Ss[ty * 4 + 0][k];
            float a1 = Ss[ty * 4 + 1][k];
            float a2 = Ss[ty * 4 + 2][k];
            float a3 = Ss[ty * 4 + 3][k];
            float4 bb = *(const float4*)&Vs[k][tx * 4];
            o[0][0] += a0 * bb.x; o[0][1] += a0 * bb.y; o[0][2] += a0 * bb.z; o[0][3] += a0 * bb.w;
            o[1][0] += a1 * bb.x; o[1][1] += a1 * bb.y; o[1][2] += a1 * bb.z; o[1][3] += a1 * bb.w;
            o[2][0] += a2 * bb.x; o[2][1] += a2 * bb.y; o[2][2] += a2 * bb.z; o[2][3] += a2 * bb.w;
            o[3][0] += a3 * bb.x; o[3][1] += a3 * bb.y; o[3][2] += a3 * bb.z; o[3][3] += a3 * bb.w;
        }
        // Write split-bf16 planes directly into g_A2 (input of K3)
#pragma unroll
        for (int i = 0; i < 4; i++) {
            __nv_bfloat16* obase = g_A2 + (size_t)tok[ty * 4 + i] * 768 + ct + tx * 4;
            uint32_t h0, l0, h1, l1;
            split2(o[i][0], o[i][1], h0, l0);
            split2(o[i][2], o[i][3], h1, l1);
            *(uint32_t*)(obase)         = h0;
            *(uint32_t*)(obase + 2)     = h1;
            *(uint32_t*)(obase + 384)   = l0;
            *(uint32_t*)(obase + 386)   = l1;
        }
        __syncthreads();
    }
}

// ---------------------------------------------------------------------------
extern "C" void kernel_launch(void* const* d_in, const int* in_sizes, int n_in,
                              void* d_out, int out_size)
{
    const float* x      = (const float*)d_in[0];
    const float* w_qkv  = (const float*)d_in[1];
    const float* b_qkv  = (const float*)d_in[2];
    const float* w_proj = (const float*)d_in[3];
    const float* b_proj = (const float*)d_in[4];
    float* out = (float*)d_out;

    float* qkv_ptr = nullptr;
    __nv_bfloat16 *a2 = nullptr, *whi1 = nullptr, *wlo1 = nullptr,
                  *whi3 = nullptr, *wlo3 = nullptr;
    cudaGetSymbolAddress((void**)&qkv_ptr, g_qkv);
    cudaGetSymbolAddress((void**)&a2,   g_A2);
    cudaGetSymbolAddress((void**)&whi1, g_Whi1);
    cudaGetSymbolAddress((void**)&wlo1, g_Wlo1);
    cudaGetSymbolAddress((void**)&whi3, g_Whi3);
    cudaGetSymbolAddress((void**)&wlo3, g_Wlo3);

    cudaFuncSetAttribute(gemm_mma, cudaFuncAttributeMaxDynamicSharedMemorySize,
                         3 * STAGE_BYTES);

    // Weight splits (tiny)
    split_w_kernel<<<(NQKV * CDIM + 255) / 256, 256>>>(w_qkv, whi1, wlo1, NQKV);
    split_w_kernel<<<(CDIM * CDIM + 255) / 256, 256>>>(w_proj, whi3, wlo3, CDIM);

    // Split x -> A2 planes
    split_x_kernel<<<TOKENS * 96 / 256, 256>>>(x, a2);

    // K1: qkv = x @ w_qkv + b_qkv
    gemm_mma<<<dim3(NQKV / 128, TOKENS / 256), 256, 3 * STAGE_BYTES>>>(
        a2, whi1, wlo1, b_qkv, qkv_ptr, NQKV);

    // K2: per-window attention (writes split planes to g_A2)
    window_attn<<<NWIN, 256>>>();

    // K3: out = att @ w_proj + b_proj
    gemm_mma<<<dim3(CDIM / 128, TOKENS / 256), 256, 3 * STAGE_BYTES>>>(
        a2, whi3, wlo3, b_proj, out, CDIM);
}

// round 8
// speedup vs baseline: 1.4733x; 1.4733x over previous
#include <cuda_runtime.h>
#include <cuda_bf16.h>
#include <cstdint>
#include <math.h>

// Problem constants (B=8, H=W=128, C=384, window=8)
#define TOKENS   131072              // 8*128*128
#define CDIM     384
#define NQKV     1152
#define NWIN     2048                // 8 * 16 * 16 windows

// ---------------------------------------------------------------------------
// Scratch (allocation-free rule: __device__ globals)
// ---------------------------------------------------------------------------
__device__ float g_qkv[(size_t)TOKENS * NQKV];   // fp32 qkv (604 MB)
__device__ float g_att[(size_t)TOKENS * CDIM];   // fp32 attention out (201 MB)
__device__ float g_Wt1[(size_t)NQKV * CDIM];     // w_qkv^T  [N][K], tf32-rounded
__device__ float g_Wt3[(size_t)CDIM * CDIM];     // w_proj^T [N][K], tf32-rounded

__device__ __forceinline__ uint32_t smem_u32(const void* p) {
    uint32_t a;
    asm("{ .reg .u64 tmp; cvta.to.shared.u64 tmp, %1; cvt.u32.u64 %0, tmp; }"
        : "=r"(a) : "l"(p));
    return a;
}

__device__ __forceinline__ void mma_tf32(float* c, const uint32_t* a,
                                         uint32_t b0, uint32_t b1) {
    asm volatile(
        "mma.sync.aligned.m16n8k8.row.col.f32.tf32.tf32.f32 "
        "{%0,%1,%2,%3}, {%4,%5,%6,%7}, {%8,%9}, {%0,%1,%2,%3};\n"
        : "+f"(c[0]), "+f"(c[1]), "+f"(c[2]), "+f"(c[3])
        : "r"(a[0]), "r"(a[1]), "r"(a[2]), "r"(a[3]), "r"(b0), "r"(b1));
}

#define LDSM_X4(r, a) \
    asm volatile("ldmatrix.sync.aligned.m8n8.x4.shared.b16 {%0,%1,%2,%3}, [%4];" \
        : "=r"((r)[0]), "=r"((r)[1]), "=r"((r)[2]), "=r"((r)[3]) : "r"(a))

#define CVT_TF32(r) \
    asm("cvt.rna.tf32.f32 %0, %0;" : "+r"(r))

// ---------------------------------------------------------------------------
// Weight transpose + tf32 rounding: w [384 x N] fp32 -> out [N x 384]
// ---------------------------------------------------------------------------
__global__ __launch_bounds__(256) void trans_w_kernel(
    const float* __restrict__ w, float* __restrict__ out, int N)
{
    const int t = blockIdx.x * 256 + threadIdx.x;
    if (t >= N * CDIM) return;
    const int n = t / CDIM;
    const int k = t % CDIM;
    uint32_t v = __float_as_uint(w[(size_t)k * N + n]);
    CVT_TF32(v);
    out[(size_t)n * CDIM + k] = __uint_as_float(v);
}

// ---------------------------------------------------------------------------
// TF32 GEMM: C[M x Ndim] = A[M x 384](fp32) @ Bt^T + bias, single pass.
//   BM=128, BN=128, BK=32 floats, 256 threads (8 warps: 4M x 2N), 2 CTAs/SM.
//   Stage = A(128 x 128B) + B(128 x 128B) = 32768 B; 3 stages = 98304 B.
//   Swizzle: 16B chunk ch of row r stored at ch ^ (r & 7).
// ---------------------------------------------------------------------------
#define STAGE_BYTES 32768u
__global__ __launch_bounds__(256, 2) void gemm_tf32(
    const float* __restrict__ A,
    const float* __restrict__ Bt,
    const float* __restrict__ bias,
    float* __restrict__ C, int Ndim)
{
    extern __shared__ __align__(16) char smem[];
    const uint32_t smemBase = smem_u32(smem);

    const int tid  = threadIdx.x;
    const int wid  = tid >> 5;
    const int lane = tid & 31;
    const int g    = lane >> 2;
    const int t4   = lane & 3;
    const int m0   = blockIdx.y * 128;
    const int n0   = blockIdx.x * 128;
    const int wm   = (wid & 3) * 32;   // warp M offset
    const int wn   = (wid >> 2) * 64;  // warp N offset

    // cp.async: 2048 chunks of 16B per stage (A 1024 + B 1024); 8 per thread
    const float* srcs[8];
    uint32_t dsts[8];
#pragma unroll
    for (int i = 0; i < 8; i++) {
        const int id = tid + i * 256;          // < 2048
        const int ab = id >> 10;               // 0 = A, 1 = B
        const int r  = (id >> 3) & 127;
        const int ch = id & 7;
        if (ab == 0) srcs[i] = A  + (size_t)(m0 + r) * CDIM + ch * 4;
        else         srcs[i] = Bt + (size_t)(n0 + r) * CDIM + ch * 4;
        dsts[i] = smemBase + (uint32_t)(ab * 16384 + r * 128 + (ch ^ (r & 7)) * 16);
    }

#define PREFETCH(s, off) do {                                                 \
        _Pragma("unroll")                                                     \
        for (int _i = 0; _i < 8; _i++) {                                      \
            asm volatile("cp.async.cg.shared.global [%0], [%1], 16;"          \
                :: "r"(dsts[_i] + (off)), "l"(srcs[_i] + (s) * 32));          \
        }                                                                     \
        asm volatile("cp.async.commit_group;" ::: "memory");                  \
    } while (0)

    // ldmatrix addressing. Lane L: row = base + (L&15); 16B chunk for k8-step q:
    //   c = 2q + (L>>4), stored at c ^ ((row)&7) = ((q ^ v)<<1) | u
    //   with u = (L>>4) ^ (L&1... ) -- precompute 4 chunk offsets per lane.
    const int la = lane & 15;
    const int h  = lane >> 4;
    const int s7 = la & 7;
    uint32_t coff[4];
#pragma unroll
    for (int q = 0; q < 4; q++)
        coff[q] = (uint32_t)((((2 * q + h) ^ s7) & 7) * 16);
    const uint32_t aBase = smemBase + (uint32_t)((wm + la) * 128);
    const uint32_t bBase = smemBase + 16384 + (uint32_t)((wn + la) * 128);

    float acc[2][8][4];
#pragma unroll
    for (int mt = 0; mt < 2; mt++)
#pragma unroll
        for (int nt = 0; nt < 8; nt++)
#pragma unroll
            for (int i = 0; i < 4; i++) acc[mt][nt][i] = 0.f;

    PREFETCH(0, 0);
    PREFETCH(1, STAGE_BYTES);

#pragma unroll
    for (int s = 0; s < 12; s++) {
        asm volatile("cp.async.wait_group 1;" ::: "memory");
        __syncthreads();
        if (s < 10) PREFETCH(s + 2, ((s + 2) % 3) * STAGE_BYTES);
        else asm volatile("cp.async.commit_group;" ::: "memory");
        const uint32_t off = (s % 3) * STAGE_BYTES;

#pragma unroll
        for (int q = 0; q < 4; q++) {              // k8 steps
            uint32_t a[2][4];
#pragma unroll
            for (int mt = 0; mt < 2; mt++) {
                LDSM_X4(a[mt], aBase + off + mt * 2048 + coff[q]);
                CVT_TF32(a[mt][0]); CVT_TF32(a[mt][1]);
                CVT_TF32(a[mt][2]); CVT_TF32(a[mt][3]);
            }
#pragma unroll
            for (int ntp = 0; ntp < 4; ntp++) {    // 16 N rows each
                uint32_t b[4];
                LDSM_X4(b, bBase + off + ntp * 2048 + coff[q]);
                // nt = ntp*2   (n rows +0..7):  {b0=b[0], b1=b[2]}
                // nt = ntp*2+1 (n rows +8..15): {b0=b[1], b1=b[3]}
                mma_tf32(acc[0][ntp * 2],     a[0], b[0], b[2]);
                mma_tf32(acc[0][ntp * 2 + 1], a[0], b[1], b[3]);
                mma_tf32(acc[1][ntp * 2],     a[1], b[0], b[2]);
                mma_tf32(acc[1][ntp * 2 + 1], a[1], b[1], b[3]);
            }
        }
    }
#undef PREFETCH

    // Epilogue: bias + store
#pragma unroll
    for (int mt = 0; mt < 2; mt++) {
        const int r0 = m0 + wm + mt * 16 + g;
#pragma unroll
        for (int nt = 0; nt < 8; nt++) {
            const int col = n0 + wn + (nt >> 1) * 16 + (nt & 1) * 8 + t4 * 2;
            float2 bv = *(const float2*)(bias + col);
            float2 v0 = make_float2(acc[mt][nt][0] + bv.x, acc[mt][nt][1] + bv.y);
            float2 v1 = make_float2(acc[mt][nt][2] + bv.x, acc[mt][nt][3] + bv.y);
            *(float2*)(C + (size_t)r0 * Ndim + col) = v0;
            *(float2*)(C + (size_t)(r0 + 8) * Ndim + col) = v1;
        }
    }
}

// ---------------------------------------------------------------------------
// Per-window attention (fp32; coalesced loads; swizzled transposed smem;
// writes fp32 g_att)
// ---------------------------------------------------------------------------
__global__ __launch_bounds__(256) void window_attn()
{
    const int gb  = blockIdx.x;
    const int b   = gb >> 8;
    const int win = gb & 255;
    const int wy  = win >> 4;
    const int wx  = win & 15;

    __shared__ int tok[64];
    __shared__ float Ss[64][65];
    __shared__ __align__(16) char raw[64 * 68 * 4];
    float (*Qs)[64] = (float(*)[64])raw;               // [32][64] swizzled cols
    float (*Ks)[64] = (float(*)[64])(raw + 8192);
    float (*Vs)[68] = (float(*)[68])raw;               // [64][68] overlay

    const int tid = threadIdx.x;
    if (tid < 64) {
        int py = tid >> 3, px = tid & 7;
        tok[tid] = b * 16384 + (wy * 8 + py) * 128 + (wx * 8 + px);
    }
    __syncthreads();

    const int tx  = tid & 15;
    const int ty  = tid >> 4;
    const int grp = tid >> 2;          // token index 0..63
    const int l   = tid & 3;           // lane-in-group

    const float* qb = g_qkv + (size_t)tok[grp] * NQKV;

    // ---- Phase 1: S = Q K^T ----
    float acc[4][4];
#pragma unroll
    for (int i = 0; i < 4; i++)
#pragma unroll
        for (int j = 0; j < 4; j++) acc[i][j] = 0.f;

    const int colq = grp ^ (l << 3);
    for (int kt = 0; kt < CDIM; kt += 32) {
        const float* qp = qb + kt + l * 8;
        float4 q0 = *(const float4*)qp;
        float4 q1 = *(const float4*)(qp + 4);
        float4 k0 = *(const float4*)(qp + CDIM);
        float4 k1 = *(const float4*)(qp + CDIM + 4);
        const int kk = l * 8;
        Qs[kk + 0][colq] = q0.x; Qs[kk + 1][colq] = q0.y;
        Qs[kk + 2][colq] = q0.z; Qs[kk + 3][colq] = q0.w;
        Qs[kk + 4][colq] = q1.x; Qs[kk + 5][colq] = q1.y;
        Qs[kk + 6][colq] = q1.z; Qs[kk + 7][colq] = q1.w;
        Ks[kk + 0][colq] = k0.x; Ks[kk + 1][colq] = k0.y;
        Ks[kk + 2][colq] = k0.z; Ks[kk + 3][colq] = k0.w;
        Ks[kk + 4][colq] = k1.x; Ks[kk + 5][colq] = k1.y;
        Ks[kk + 6][colq] = k1.z; Ks[kk + 7][colq] = k1.w;
        __syncthreads();
#pragma unroll
        for (int k = 0; k < 32; k++) {
            const int xv = k & 24;
            float4 a  = *(const float4*)&Qs[k][(ty * 4) ^ xv];
            float4 bb = *(const float4*)&Ks[k][(tx * 4) ^ xv];
            float av[4] = {a.x, a.y, a.z, a.w};
            float bv[4] = {bb.x, bb.y, bb.z, bb.w};
#pragma unroll
            for (int i = 0; i < 4; i++)
#pragma unroll
                for (int j = 0; j < 4; j++) acc[i][j] += av[i] * bv[j];
        }
        __syncthreads();
    }
#pragma unroll
    for (int i = 0; i < 4; i++)
#pragma unroll
        for (int j = 0; j < 4; j++) Ss[ty * 4 + i][tx * 4 + j] = acc[i][j];
    __syncthreads();

    // ---- Phase 2: softmax rows ----
    if (tid < 64) {
        float m = -1e30f;
#pragma unroll 8
        for (int j = 0; j < 64; j++) m = fmaxf(m, Ss[tid][j]);
        float s = 0.f;
#pragma unroll 8
        for (int j = 0; j < 64; j++) {
            float e = expf(Ss[tid][j] - m);
            Ss[tid][j] = e;
            s += e;
        }
        float inv = 1.f / s;
#pragma unroll 8
        for (int j = 0; j < 64; j++) Ss[tid][j] *= inv;
    }
    __syncthreads();

    // ---- Phase 3: O = P V ----
    for (int ct = 0; ct < CDIM; ct += 64) {
        const float* vp = qb + 2 * CDIM + ct;
#pragma unroll
        for (int u = 0; u < 4; u++) {
            float4 v = *(const float4*)(vp + u * 16 + l * 4);
            *(float4*)&Vs[grp][u * 16 + l * 4] = v;
        }
        __syncthreads();

        float o[4][4];
#pragma unroll
        for (int i = 0; i < 4; i++)
#pragma unroll
            for (int j = 0; j < 4; j++) o[i][j] = 0.f;
#pragma unroll
        for (int k = 0; k < 64; k++) {
            float a0 = Ss[ty * 4 + 0][k];
            float a1 = Ss[ty * 4 + 1][k];
            float a2 = Ss[ty * 4 + 2][k];
            float a3 = Ss[ty * 4 + 3][k];
            float4 bb = *(const float4*)&Vs[k][tx * 4];
            o[0][0] += a0 * bb.x; o[0][1] += a0 * bb.y; o[0][2] += a0 * bb.z; o[0][3] += a0 * bb.w;
            o[1][0] += a1 * bb.x; o[1][1] += a1 * bb.y; o[1][2] += a1 * bb.z; o[1][3] += a1 * bb.w;
            o[2][0] += a2 * bb.x; o[2][1] += a2 * bb.y; o[2][2] += a2 * bb.z; o[2][3] += a2 * bb.w;
            o[3][0] += a3 * bb.x; o[3][1] += a3 * bb.y; o[3][2] += a3 * bb.z; o[3][3] += a3 * bb.w;
        }
#pragma unroll
        for (int i = 0; i < 4; i++) {
            float* orow = g_att + (size_t)tok[ty * 4 + i] * CDIM + ct + tx * 4;
            *(float4*)orow = make_float4(o[i][0], o[i][1], o[i][2], o[i][3]);
        }
        __syncthreads();
    }
}

// ---------------------------------------------------------------------------
extern "C" void kernel_launch(void* const* d_in, const int* in_sizes, int n_in,
                              void* d_out, int out_size)
{
    const float* x      = (const float*)d_in[0];
    const float* w_qkv  = (const float*)d_in[1];
    const float* b_qkv  = (const float*)d_in[2];
    const float* w_proj = (const float*)d_in[3];
    const float* b_proj = (const float*)d_in[4];
    float* out = (float*)d_out;

    float *qkv_ptr = nullptr, *att_ptr = nullptr, *wt1 = nullptr, *wt3 = nullptr;
    cudaGetSymbolAddress((void**)&qkv_ptr, g_qkv);
    cudaGetSymbolAddress((void**)&att_ptr, g_att);
    cudaGetSymbolAddress((void**)&wt1, g_Wt1);
    cudaGetSymbolAddress((void**)&wt3, g_Wt3);

    cudaFuncSetAttribute(gemm_tf32, cudaFuncAttributeMaxDynamicSharedMemorySize,
                         3 * STAGE_BYTES);

    // Weight transposes (tiny)
    trans_w_kernel<<<(NQKV * CDIM + 255) / 256, 256>>>(w_qkv, wt1, NQKV);
    trans_w_kernel<<<(CDIM * CDIM + 255) / 256, 256>>>(w_proj, wt3, CDIM);

    // K1: qkv = x @ w_qkv + b_qkv  (reads x fp32 directly)
    gemm_tf32<<<dim3(NQKV / 128, TOKENS / 128), 256, 3 * STAGE_BYTES>>>(
        x, wt1, b_qkv, qkv_ptr, NQKV);

    // K2: per-window attention (fp32 in/out)
    window_attn<<<NWIN, 256>>>();

    // K3: out = att @ w_proj + b_proj
    gemm_tf32<<<dim3(CDIM / 128, TOKENS / 128), 256, 3 * STAGE_BYTES>>>(
        att_ptr, wt3, b_proj, out, CDIM);
}